// round 2
// baseline (speedup 1.0000x reference)
#include <cuda_runtime.h>
#include <math.h>

// Problem constants
#define Bv 2
#define Sv 2048
#define Ev 1024
#define Hv 16
#define Dv 64
#define N3 3072           // 3*E
#define BHv 32            // B*H

// ---------------- device scratch (static, allocation-free) ----------------
__device__ float g_Q[Bv*Hv*Sv*Dv];
__device__ float g_K[Bv*Hv*Sv*Dv];
__device__ float g_V[Bv*Hv*Sv*Dv];
__device__ float g_AO[Bv*Sv*Ev];
__device__ float g_rowmax[BHv*Sv];
__device__ float g_rowsum[BHv*Sv];
// Fallback weights scratch in case d_out only holds attn_out
__device__ float g_Wscratch[(size_t)Bv*Hv*Sv*Sv];

// ============================================================
// Kernel 1: QKV GEMM  [4096,1024] @ [1024,3072] + bias
// 128x128x8 tiles, 256 threads, 8x8 microtile, double-buffered smem.
// Epilogue scatters into g_Q/g_K/g_V in [B,H,S,D] layout.
// ============================================================
__global__ void __launch_bounds__(256) qkv_gemm(const float* __restrict__ A,
                                                const float* __restrict__ W,
                                                const float* __restrict__ bias) {
    const int N = N3;          // 3072
    const int K = Ev;          // 1024
    __shared__ float As[2][8][128];
    __shared__ float Bs[2][8][128];

    int bx = blockIdx.x;       // N tile
    int by = blockIdx.y;       // M tile
    int tid = threadIdx.x;
    int tr = tid / 16;         // 0..15
    int tc = tid % 16;         // 0..15

    float acc[8][8];
#pragma unroll
    for (int i = 0; i < 8; i++)
#pragma unroll
        for (int j = 0; j < 8; j++) acc[i][j] = 0.f;

    int arow = tid >> 1;            // 0..127
    int acol = (tid & 1) * 4;       // 0 or 4
    int brow = tid >> 5;            // 0..7
    int bcol = (tid & 31) * 4;      // 0..124

    const float* Ag = A + (size_t)(by * 128 + arow) * K + acol;
    const float* Bg = W + (size_t)brow * N + bx * 128 + bcol;

    {
        float4 a = *(const float4*)Ag;
        float4 b = *(const float4*)Bg;
        As[0][acol + 0][arow] = a.x;
        As[0][acol + 1][arow] = a.y;
        As[0][acol + 2][arow] = a.z;
        As[0][acol + 3][arow] = a.w;
        *(float4*)&Bs[0][brow][bcol] = b;
    }
    __syncthreads();

    for (int k0 = 0; k0 < K; k0 += 8) {
        int buf = (k0 >> 3) & 1;
        bool more = (k0 + 8) < K;
        float4 na, nb;
        if (more) {
            na = *(const float4*)(Ag + k0 + 8);
            nb = *(const float4*)(Bg + (size_t)(k0 + 8) * N);
        }
#pragma unroll
        for (int kk = 0; kk < 8; kk++) {
            float ra[8], rb[8];
            *(float4*)&ra[0] = *(const float4*)&As[buf][kk][tr * 8];
            *(float4*)&ra[4] = *(const float4*)&As[buf][kk][tr * 8 + 4];
            *(float4*)&rb[0] = *(const float4*)&Bs[buf][kk][tc * 8];
            *(float4*)&rb[4] = *(const float4*)&Bs[buf][kk][tc * 8 + 4];
#pragma unroll
            for (int i = 0; i < 8; i++)
#pragma unroll
                for (int j = 0; j < 8; j++) acc[i][j] += ra[i] * rb[j];
        }
        if (more) {
            int nb2 = buf ^ 1;
            As[nb2][acol + 0][arow] = na.x;
            As[nb2][acol + 1][arow] = na.y;
            As[nb2][acol + 2][arow] = na.z;
            As[nb2][acol + 3][arow] = na.w;
            *(float4*)&Bs[nb2][brow][bcol] = nb;
            __syncthreads();
        }
    }

    // Scatter epilogue
#pragma unroll
    for (int i = 0; i < 8; i++) {
        int m = by * 128 + tr * 8 + i;
        int b = m / Sv, s = m % Sv;
#pragma unroll
        for (int j = 0; j < 8; j++) {
            int n = bx * 128 + tc * 8 + j;
            float v = acc[i][j] + bias[n];
            int which = n >> 10;          // 0=q 1=k 2=v
            int e = n & 1023;
            int h = e >> 6;
            int d = e & 63;
            size_t dst = (((size_t)b * Hv + h) * Sv + s) * Dv + d;
            if (which == 0) g_Q[dst] = v;
            else if (which == 1) g_K[dst] = v;
            else g_V[dst] = v;
        }
    }
}

// ============================================================
// Kernel 2: fused scores + online softmax stats.
// One block per (row_tile of 128, bh). Loops over all column tiles:
//   - computes raw scaled+masked scores (masked -> -1e30), writes them
//   - maintains per-row online max & sum(exp) in registers
//   - zero-fills the strictly-upper tiles (balances load)
// Emits g_rowmax / g_rowsum.
// Dynamic smem: QsT[64][128] + KsT[64][128] = 64 KB.
// ============================================================
__global__ void __launch_bounds__(256) scores_fused(float* __restrict__ Wout) {
    int bh = blockIdx.y;
    int rt = (gridDim.x - 1) - blockIdx.x;   // heavy row-tiles first
    int r0 = rt * 128;
    float* out = Wout + (size_t)bh * Sv * Sv;
    int tid = threadIdx.x;
    int tr = tid / 16, tc = tid % 16;

    extern __shared__ float sm[];
    float(*QsT)[128] = (float(*)[128])sm;             // [64][128]
    float(*KsT)[128] = (float(*)[128])(sm + 64 * 128);

    const float* Q = g_Q + (size_t)bh * Sv * Dv;
    const float* Kp = g_K + (size_t)bh * Sv * Dv;

    // Load Q tile (rows r0..r0+127), transposed
#pragma unroll
    for (int it = 0; it < 8; it++) {
        int idx = tid + it * 256;      // 2048 float4
        int row = idx >> 4;            // 0..127
        int k4 = idx & 15;             // 0..15
        float4 q = *(const float4*)(Q + (size_t)(r0 + row) * Dv + k4 * 4);
        QsT[k4 * 4 + 0][row] = q.x;
        QsT[k4 * 4 + 1][row] = q.y;
        QsT[k4 * 4 + 2][row] = q.z;
        QsT[k4 * 4 + 3][row] = q.w;
    }

    float m[8], s[8];
#pragma unroll
    for (int i = 0; i < 8; i++) { m[i] = -1e30f; s[i] = 0.f; }

    const float scale = 0.125f;   // 1/sqrt(64)

    for (int c0 = 0; c0 <= r0; c0 += 128) {
        __syncthreads();   // previous tile fully consumed (also orders QsT load)
#pragma unroll
        for (int it = 0; it < 8; it++) {
            int idx = tid + it * 256;
            int row = idx >> 4;
            int k4 = idx & 15;
            float4 k = *(const float4*)(Kp + (size_t)(c0 + row) * Dv + k4 * 4);
            KsT[k4 * 4 + 0][row] = k.x;
            KsT[k4 * 4 + 1][row] = k.y;
            KsT[k4 * 4 + 2][row] = k.z;
            KsT[k4 * 4 + 3][row] = k.w;
        }
        __syncthreads();

        float acc[8][8];
#pragma unroll
        for (int i = 0; i < 8; i++)
#pragma unroll
            for (int j = 0; j < 8; j++) acc[i][j] = 0.f;

#pragma unroll 16
        for (int kk = 0; kk < 64; kk++) {
            float ra[8], rb[8];
            *(float4*)&ra[0] = *(const float4*)&QsT[kk][tr * 8];
            *(float4*)&ra[4] = *(const float4*)&QsT[kk][tr * 8 + 4];
            *(float4*)&rb[0] = *(const float4*)&KsT[kk][tc * 8];
            *(float4*)&rb[4] = *(const float4*)&KsT[kk][tc * 8 + 4];
#pragma unroll
            for (int i = 0; i < 8; i++)
#pragma unroll
                for (int j = 0; j < 8; j++) acc[i][j] += ra[i] * rb[j];
        }

        bool diag = (c0 == r0);
#pragma unroll
        for (int i = 0; i < 8; i++) {
            int r = r0 + tr * 8 + i;
            float rv[8];
#pragma unroll
            for (int j = 0; j < 8; j++) {
                int c = c0 + tc * 8 + j;
                float v = acc[i][j] * scale;
                rv[j] = (!diag || c <= r) ? v : -1e30f;
            }
            float* op = out + (size_t)r * Sv + c0 + tc * 8;
            *(float4*)op = make_float4(rv[0], rv[1], rv[2], rv[3]);
            *(float4*)(op + 4) = make_float4(rv[4], rv[5], rv[6], rv[7]);

            // online max/sum across the 16 tc-lanes (contiguous half-warp)
            float tmax = rv[0];
#pragma unroll
            for (int j = 1; j < 8; j++) tmax = fmaxf(tmax, rv[j]);
#pragma unroll
            for (int o = 8; o; o >>= 1)
                tmax = fmaxf(tmax, __shfl_xor_sync(0xffffffffu, tmax, o));
            float mnew = fmaxf(m[i], tmax);
            float ps = 0.f;
#pragma unroll
            for (int j = 0; j < 8; j++) ps += __expf(rv[j] - mnew);
#pragma unroll
            for (int o = 8; o; o >>= 1)
                ps += __shfl_xor_sync(0xffffffffu, ps, o);
            s[i] = s[i] * __expf(m[i] - mnew) + ps;
            m[i] = mnew;
        }
    }

    if (tc == 0) {
#pragma unroll
        for (int i = 0; i < 8; i++) {
            int r = r0 + tr * 8 + i;
            g_rowmax[bh * Sv + r] = m[i];
            g_rowsum[bh * Sv + r] = s[i];
        }
    }

    // Zero-fill strictly-upper tiles (final weight value there is exactly 0)
    float4 z = make_float4(0.f, 0.f, 0.f, 0.f);
    for (int c0 = r0 + 128; c0 < Sv; c0 += 128) {
#pragma unroll
        for (int it = 0; it < 16; it++) {
            int idx = tid + it * 256;          // 4096 float4
            int row = idx >> 5;                // 32 float4 per row
            int c4 = idx & 31;
            *(float4*)(out + (size_t)(r0 + row) * Sv + c0 + c4 * 4) = z;
        }
    }
}

// ============================================================
// Kernel 3: fused softmax-apply + PV.
// Reads raw scores, converts to normalized weights (writes them back
// in place = final attn_weights output), accumulates P@V into g_AO.
// Tile: 256 rows x 64 cols, 8x8 per thread, 32-wide K steps.
// ============================================================
__global__ void __launch_bounds__(256) pv_fused(float* __restrict__ Wts) {
    int bh = blockIdx.y;
    int rt = (gridDim.x - 1) - blockIdx.x;   // heavy row-tiles first
    int r0 = rt * 256;
    float* P = Wts + (size_t)bh * Sv * Sv;
    const float* V = g_V + (size_t)bh * Sv * Dv;

    __shared__ float Ps[256][33];   // [row][kk], pad 33 -> conflict-free
    __shared__ float Vs[32][72];    // [kk][col], pad 72 keeps 16B align
    __shared__ float rowm[256];
    __shared__ float rowinv[256];

    int tid = threadIdx.x;
    int tr = tid / 8;    // 0..31  (8 rows each)
    int tc = tid % 8;    // 0..7   (8 cols each)

    if (tid < 256) {
        rowm[tid] = g_rowmax[bh * Sv + r0 + tid];
        rowinv[tid] = 1.0f / g_rowsum[bh * Sv + r0 + tid];
    }

    float acc[8][8];
#pragma unroll
    for (int i = 0; i < 8; i++)
#pragma unroll
        for (int j = 0; j < 8; j++) acc[i][j] = 0.f;

    int kend = r0 + 256;
    for (int kc = 0; kc < kend; kc += 32) {
        __syncthreads();   // previous tile consumed (also covers rowm init)
        // Load + transform P tile: raw -> exp(raw-m)*inv (masked -> 0),
        // write normalized weights back to gmem, store transposed in smem.
#pragma unroll
        for (int it = 0; it < 8; it++) {
            int idx = tid + it * 256;      // 2048 float4
            int row = idx >> 3;            // 0..255
            int c4 = idx & 7;              // 0..7
            int r = r0 + row;
            float* gp = P + (size_t)r * Sv + kc + c4 * 4;
            float4 raw = *(const float4*)gp;
            float mm = rowm[row];
            float inv = rowinv[row];
            int c = kc + c4 * 4;
            float w0 = (c + 0 <= r) ? __expf(raw.x - mm) * inv : 0.f;
            float w1 = (c + 1 <= r) ? __expf(raw.y - mm) * inv : 0.f;
            float w2 = (c + 2 <= r) ? __expf(raw.z - mm) * inv : 0.f;
            float w3 = (c + 3 <= r) ? __expf(raw.w - mm) * inv : 0.f;
            *(float4*)gp = make_float4(w0, w1, w2, w3);
            Ps[row][c4 * 4 + 0] = w0;
            Ps[row][c4 * 4 + 1] = w1;
            Ps[row][c4 * 4 + 2] = w2;
            Ps[row][c4 * 4 + 3] = w3;
        }
#pragma unroll
        for (int it = 0; it < 2; it++) {
            int idx = tid + it * 256;      // 512 float4
            int row = idx >> 4;            // 0..31
            int c4 = idx & 15;             // 0..15
            *(float4*)&Vs[row][c4 * 4] =
                *(const float4*)(V + (size_t)(kc + row) * Dv + c4 * 4);
        }
        __syncthreads();

#pragma unroll
        for (int kk = 0; kk < 32; kk++) {
            float rb[8];
            *(float4*)&rb[0] = *(const float4*)&Vs[kk][tc * 8];
            *(float4*)&rb[4] = *(const float4*)&Vs[kk][tc * 8 + 4];
            float p[8];
#pragma unroll
            for (int i = 0; i < 8; i++) p[i] = Ps[tr * 8 + i][kk];
#pragma unroll
            for (int i = 0; i < 8; i++)
#pragma unroll
                for (int j = 0; j < 8; j++) acc[i][j] += p[i] * rb[j];
        }
    }

    int b = bh >> 4, h = bh & 15;
#pragma unroll
    for (int i = 0; i < 8; i++) {
        int r = r0 + tr * 8 + i;
        float* op = g_AO + ((size_t)(b * Sv + r)) * Ev + h * Dv + tc * 8;
        *(float4*)op = make_float4(acc[i][0], acc[i][1], acc[i][2], acc[i][3]);
        *(float4*)(op + 4) =
            make_float4(acc[i][4], acc[i][5], acc[i][6], acc[i][7]);
    }
}

// ============================================================
// Kernel 4: projection  g_AO[4096,1024] @ w_proj[1024,1024] + b_proj
// Double-buffered, writes d_out attn_out region [B,S,E].
// ============================================================
__global__ void __launch_bounds__(256) proj_gemm(const float* __restrict__ W,
                                                 const float* __restrict__ bias,
                                                 float* __restrict__ C) {
    const int N = Ev;          // 1024
    const int K = Ev;          // 1024
    __shared__ float As[2][8][128];
    __shared__ float Bs[2][8][128];

    int bx = blockIdx.x;
    int by = blockIdx.y;
    int tid = threadIdx.x;
    int tr = tid / 16, tc = tid % 16;

    float acc[8][8];
#pragma unroll
    for (int i = 0; i < 8; i++)
#pragma unroll
        for (int j = 0; j < 8; j++) acc[i][j] = 0.f;

    int arow = tid >> 1;
    int acol = (tid & 1) * 4;
    int brow = tid >> 5;
    int bcol = (tid & 31) * 4;

    const float* Ag = g_AO + (size_t)(by * 128 + arow) * K + acol;
    const float* Bg = W + (size_t)brow * N + bx * 128 + bcol;

    {
        float4 a = *(const float4*)Ag;
        float4 b = *(const float4*)Bg;
        As[0][acol + 0][arow] = a.x;
        As[0][acol + 1][arow] = a.y;
        As[0][acol + 2][arow] = a.z;
        As[0][acol + 3][arow] = a.w;
        *(float4*)&Bs[0][brow][bcol] = b;
    }
    __syncthreads();

    for (int k0 = 0; k0 < K; k0 += 8) {
        int buf = (k0 >> 3) & 1;
        bool more = (k0 + 8) < K;
        float4 na, nb;
        if (more) {
            na = *(const float4*)(Ag + k0 + 8);
            nb = *(const float4*)(Bg + (size_t)(k0 + 8) * N);
        }
#pragma unroll
        for (int kk = 0; kk < 8; kk++) {
            float ra[8], rb[8];
            *(float4*)&ra[0] = *(const float4*)&As[buf][kk][tr * 8];
            *(float4*)&ra[4] = *(const float4*)&As[buf][kk][tr * 8 + 4];
            *(float4*)&rb[0] = *(const float4*)&Bs[buf][kk][tc * 8];
            *(float4*)&rb[4] = *(const float4*)&Bs[buf][kk][tc * 8 + 4];
#pragma unroll
            for (int i = 0; i < 8; i++)
#pragma unroll
                for (int j = 0; j < 8; j++) acc[i][j] += ra[i] * rb[j];
        }
        if (more) {
            int nb2 = buf ^ 1;
            As[nb2][acol + 0][arow] = na.x;
            As[nb2][acol + 1][arow] = na.y;
            As[nb2][acol + 2][arow] = na.z;
            As[nb2][acol + 3][arow] = na.w;
            *(float4*)&Bs[nb2][brow][bcol] = nb;
            __syncthreads();
        }
    }

    float bsv[8];
#pragma unroll
    for (int j = 0; j < 8; j++) bsv[j] = bias[bx * 128 + tc * 8 + j];

#pragma unroll
    for (int i = 0; i < 8; i++) {
        int mrow = by * 128 + tr * 8 + i;
        float* cr = C + (size_t)mrow * N + bx * 128 + tc * 8;
        *(float4*)cr = make_float4(acc[i][0] + bsv[0], acc[i][1] + bsv[1],
                                   acc[i][2] + bsv[2], acc[i][3] + bsv[3]);
        *(float4*)(cr + 4) = make_float4(acc[i][4] + bsv[4], acc[i][5] + bsv[5],
                                         acc[i][6] + bsv[6], acc[i][7] + bsv[7]);
    }
}

// ============================================================
// Launch
// ============================================================
extern "C" void kernel_launch(void* const* d_in, const int* in_sizes, int n_in,
                              void* d_out, int out_size) {
    const float* hs     = (const float*)d_in[0];
    const float* w_attn = (const float*)d_in[1];
    const float* b_attn = (const float*)d_in[2];
    const float* w_proj = (const float*)d_in[3];
    const float* b_proj = (const float*)d_in[4];
    float* out = (float*)d_out;

    const size_t AO_N = (size_t)Bv * Sv * Ev;               // 4,194,304
    const size_t W_N  = (size_t)Bv * Hv * Sv * Sv;          // 134,217,728

    float* wts;
    if ((size_t)out_size >= AO_N + W_N) {
        wts = out + AO_N;          // weights live directly in d_out
    } else {
        void* p = nullptr;
        cudaGetSymbolAddress(&p, g_Wscratch);
        wts = (float*)p;
    }

    // scores kernel needs 64 KB dynamic smem
    cudaFuncSetAttribute(scores_fused,
                         cudaFuncAttributeMaxDynamicSharedMemorySize, 65536);

    qkv_gemm<<<dim3(N3 / 128, (Bv * Sv) / 128), 256>>>(hs, w_attn, b_attn);
    scores_fused<<<dim3(Sv / 128, BHv), 256, 65536>>>(wts);
    pv_fused<<<dim3(Sv / 256, BHv), 256>>>(wts);
    proj_gemm<<<dim3(Ev / 128, (Bv * Sv) / 128), 256>>>(w_proj, b_proj, out);
}

// round 4
// speedup vs baseline: 3.3580x; 3.3580x over previous
#include <cuda_runtime.h>
#include <math.h>
#include <cstdint>

// Problem constants
#define Bv 2
#define Sv 2048
#define Ev 1024
#define Hv 16
#define Dv 64
#define N3 3072
#define BHv 32
#define KDIM 1024

// ---------------- device scratch (static, allocation-free) ----------------
__device__ float g_HR[Bv*Sv*Ev];           // tf32-rounded hidden
__device__ float g_Q[Bv*Hv*Sv*Dv];
__device__ float g_K[Bv*Hv*Sv*Dv];
__device__ float g_V[Bv*Hv*Sv*Dv];
__device__ float g_AO[Bv*Sv*Ev];
__device__ float g_WAT[(size_t)N3*Ev];     // w_attn^T (tf32-rounded)
__device__ float g_WPT[(size_t)Ev*Ev];     // w_proj^T (tf32-rounded)
__device__ float g_Wscratch[(size_t)Bv*Hv*Sv*Sv];

// ==================== helpers ====================
__device__ __forceinline__ uint32_t smem_u32(const void* p) {
    uint32_t a;
    asm("{ .reg .u64 t; cvta.to.shared.u64 t, %1; cvt.u32.u64 %0, t; }"
        : "=r"(a) : "l"(p));
    return a;
}
__device__ __forceinline__ uint32_t cvt_tf32(float f) {
    uint32_t o;
    asm("cvt.rna.tf32.f32 %0, %1;" : "=r"(o) : "f"(f));
    return o;
}
__device__ __forceinline__ float tf32f(float f) {
    return __uint_as_float(cvt_tf32(f));
}
#define CP16(dst, src) \
    asm volatile("cp.async.cg.shared.global [%0], [%1], 16;" \
                 :: "r"(dst), "l"(src) : "memory")
#define CP_COMMIT() asm volatile("cp.async.commit_group;" ::: "memory")
#define CP_WAIT1()  asm volatile("cp.async.wait_group 1;" ::: "memory")
#define CP_WAIT0()  asm volatile("cp.async.wait_group 0;" ::: "memory")

#define MMA_TF32(d, a, b) \
    asm volatile("mma.sync.aligned.m16n8k8.row.col.f32.tf32.tf32.f32 " \
        "{%0,%1,%2,%3}, {%4,%5,%6,%7}, {%8,%9}, {%0,%1,%2,%3};" \
        : "+f"((d).x), "+f"((d).y), "+f"((d).z), "+f"((d).w) \
        : "r"((a)[0]), "r"((a)[1]), "r"((a)[2]), "r"((a)[3]), \
          "r"((b)[0]), "r"((b)[1]))

// ============================================================
// Pre-pass: round a float array to tf32 (rna) into dst.
// ============================================================
__global__ void __launch_bounds__(256) round_tf32_kernel(const float* __restrict__ src,
                                                         float* __restrict__ dst) {
    int i = blockIdx.x * 256 + threadIdx.x;
    float4 v = ((const float4*)src)[i];
    v.x = tf32f(v.x); v.y = tf32f(v.y); v.z = tf32f(v.z); v.w = tf32f(v.w);
    ((float4*)dst)[i] = v;
}

// ============================================================
// Transpose + tf32 rounding: src[R][C] -> dst[C][R]
// ============================================================
__global__ void transpose_k(const float* __restrict__ src, float* __restrict__ dst,
                            int R, int C) {
    __shared__ float t[32][33];
    int bx = blockIdx.x * 32, by = blockIdx.y * 32;
    int x = bx + threadIdx.x;
#pragma unroll
    for (int i = threadIdx.y; i < 32; i += 8)
        t[i][threadIdx.x] = src[(size_t)(by + i) * C + x];
    __syncthreads();
    int x2 = by + threadIdx.x;
#pragma unroll
    for (int i = threadIdx.y; i < 32; i += 8)
        dst[(size_t)(bx + i) * R + x2] = tf32f(t[threadIdx.x][i]);
}

// ============================================================
// Shared GEMM mainloop: 128x128 tile, K=1024, BK=16, 8 warps,
// warp tile 64x32, mma m16n8k8 tf32. Dynamic smem 40960 B:
//   As[2][128][20] at 0, Bs[2][128][20] at 5120 floats.
// Inputs must already be tf32-rounded in gmem.
// ============================================================
__device__ __forceinline__ void gemm_loop_1024(const float* __restrict__ Ag,
                                               const float* __restrict__ Bg,
                                               float* sm, float4 acc[4][4]) {
    int tid = threadIdx.x, lane = tid & 31, wid = tid >> 5;
    int wm = wid >> 2, wn = wid & 3;
    int lr = lane >> 2, lc = lane & 3;

    const int PITCH = 20;
    const int ABUF = 128 * PITCH;          // 2560 floats
    float* As = sm;                        // [2][128][20]
    float* Bs = sm + 2 * ABUF;             // [2][128][20]

    int ldr = tid >> 2;                    // 0..63
    int ldc4 = tid & 3;                    // 0..3

#pragma unroll
    for (int i = 0; i < 4; i++)
#pragma unroll
        for (int j = 0; j < 4; j++) acc[i][j] = make_float4(0.f, 0.f, 0.f, 0.f);

    // prologue: stage 0
    {
#pragma unroll
        for (int h2 = 0; h2 < 2; h2++) {
            int row = ldr + h2 * 64;
            CP16(smem_u32(As + row * PITCH + ldc4 * 4),
                 Ag + (size_t)row * KDIM + ldc4 * 4);
            CP16(smem_u32(Bs + row * PITCH + ldc4 * 4),
                 Bg + (size_t)row * KDIM + ldc4 * 4);
        }
        CP_COMMIT();
    }

    const int NIT = KDIM / 16;   // 64
    for (int it = 0; it < NIT; it++) {
        int buf = it & 1;
        if (it + 1 < NIT) {
            int k0 = (it + 1) * 16;
            int nb = buf ^ 1;
#pragma unroll
            for (int h2 = 0; h2 < 2; h2++) {
                int row = ldr + h2 * 64;
                CP16(smem_u32(As + nb * ABUF + row * PITCH + ldc4 * 4),
                     Ag + (size_t)row * KDIM + k0 + ldc4 * 4);
                CP16(smem_u32(Bs + nb * ABUF + row * PITCH + ldc4 * 4),
                     Bg + (size_t)row * KDIM + k0 + ldc4 * 4);
            }
            CP_COMMIT();
            CP_WAIT1();
        } else {
            CP_WAIT0();
        }
        __syncthreads();

        const float* Ab = As + buf * ABUF;
        const float* Bb = Bs + buf * ABUF;
#pragma unroll
        for (int kk = 0; kk < 16; kk += 8) {
            uint32_t af[4][4];
#pragma unroll
            for (int mt = 0; mt < 4; mt++) {
                int row = wm * 64 + mt * 16 + lr;
                af[mt][0] = __float_as_uint(Ab[row * PITCH + kk + lc]);
                af[mt][1] = __float_as_uint(Ab[(row + 8) * PITCH + kk + lc]);
                af[mt][2] = __float_as_uint(Ab[row * PITCH + kk + lc + 4]);
                af[mt][3] = __float_as_uint(Ab[(row + 8) * PITCH + kk + lc + 4]);
            }
            uint32_t bf[4][2];
#pragma unroll
            for (int nt = 0; nt < 4; nt++) {
                int n = wn * 32 + nt * 8 + lr;
                bf[nt][0] = __float_as_uint(Bb[n * PITCH + kk + lc]);
                bf[nt][1] = __float_as_uint(Bb[n * PITCH + kk + lc + 4]);
            }
#pragma unroll
            for (int mt = 0; mt < 4; mt++)
#pragma unroll
                for (int nt = 0; nt < 4; nt++)
                    MMA_TF32(acc[mt][nt], af[mt], bf[nt]);
        }
        __syncthreads();
    }
}

// ============================================================
// Kernel 1: QKV GEMM (mma tf32). A = g_HR, B = g_WAT.
// Epilogue: + bias, tf32-round, scatter into g_Q/g_K/g_V [B,H,S,D].
// ============================================================
__global__ void __launch_bounds__(256) qkv_gemm_mma(const float* __restrict__ bias) {
    extern __shared__ float sm[];
    int m0 = blockIdx.y * 128, n0 = blockIdx.x * 128;
    float4 acc[4][4];
    gemm_loop_1024(g_HR + (size_t)m0 * KDIM, g_WAT + (size_t)n0 * KDIM, sm, acc);

    int lane = threadIdx.x & 31, wid = threadIdx.x >> 5;
    int wm = wid >> 2, wn = wid & 3;
    int lr = lane >> 2, lc = lane & 3;

#pragma unroll
    for (int mt = 0; mt < 4; mt++) {
#pragma unroll
        for (int nt = 0; nt < 4; nt++) {
            int col = n0 + wn * 32 + nt * 8 + lc * 2;
            int which = col >> 10;
            int e = col & 1023;
            int h = e >> 6, d = e & 63;
            float* dstb = (which == 0) ? g_Q : (which == 1) ? g_K : g_V;
            float b0 = bias[col], b1 = bias[col + 1];
#pragma unroll
            for (int half = 0; half < 2; half++) {
                int row = m0 + wm * 64 + mt * 16 + lr + half * 8;
                int b = row >> 11, s = row & 2047;
                float* dp = dstb + (((size_t)b * Hv + h) * Sv + s) * Dv + d;
                float v0 = (half ? acc[mt][nt].z : acc[mt][nt].x) + b0;
                float v1 = (half ? acc[mt][nt].w : acc[mt][nt].y) + b1;
                float2 o = make_float2(tf32f(v0), tf32f(v1));
                *(float2*)dp = o;
            }
        }
    }
}

// ============================================================
// Kernel 5: projection (mma tf32). A = g_AO, B = g_WPT. -> d_out.
// ============================================================
__global__ void __launch_bounds__(256) proj_gemm_mma(const float* __restrict__ bias,
                                                     float* __restrict__ C) {
    extern __shared__ float sm[];
    int m0 = blockIdx.y * 128, n0 = blockIdx.x * 128;
    float4 acc[4][4];
    gemm_loop_1024(g_AO + (size_t)m0 * KDIM, g_WPT + (size_t)n0 * KDIM, sm, acc);

    int lane = threadIdx.x & 31, wid = threadIdx.x >> 5;
    int wm = wid >> 2, wn = wid & 3;
    int lr = lane >> 2, lc = lane & 3;

#pragma unroll
    for (int mt = 0; mt < 4; mt++) {
#pragma unroll
        for (int nt = 0; nt < 4; nt++) {
            int col = n0 + wn * 32 + nt * 8 + lc * 2;
            float b0 = bias[col], b1 = bias[col + 1];
#pragma unroll
            for (int half = 0; half < 2; half++) {
                int row = m0 + wm * 64 + mt * 16 + lr + half * 8;
                float v0 = (half ? acc[mt][nt].z : acc[mt][nt].x) + b0;
                float v1 = (half ? acc[mt][nt].w : acc[mt][nt].y) + b1;
                *(float2*)(C + (size_t)row * Ev + col) = make_float2(v0, v1);
            }
        }
    }
}

// ============================================================
// Kernel 2: scores (mma tf32) = (Q K^T)/8, causal mask -> 0.
// 128x128 tile per block; K=64 loaded once. Upper tiles: zero-fill.
// Dynamic smem: Qs[128][68] + Ks[128][68] = 69632 B.
// ============================================================
__global__ void __launch_bounds__(256) scores_mma(float* __restrict__ Wout) {
    int bh = blockIdx.z;
    int c0 = blockIdx.x * 128;
    int r0 = blockIdx.y * 128;
    float* out = Wout + (size_t)bh * Sv * Sv;
    int tid = threadIdx.x;

    if (c0 > r0) {   // fully masked (tile-aligned): weights are exactly 0
        float4 z = make_float4(0.f, 0.f, 0.f, 0.f);
#pragma unroll
        for (int it = 0; it < 16; it++) {
            int idx = tid + it * 256;
            int row = idx >> 5;
            int c4 = idx & 31;
            *(float4*)(out + (size_t)(r0 + row) * Sv + c0 + c4 * 4) = z;
        }
        return;
    }

    extern __shared__ float sm[];
    const int PITCH = 68;
    float* Qs = sm;                   // [128][68]
    float* Ks = sm + 128 * PITCH;

    const float* Q = g_Q + (size_t)bh * Sv * Dv;
    const float* Kp = g_K + (size_t)bh * Sv * Dv;

#pragma unroll
    for (int it = 0; it < 8; it++) {
        int idx = tid + it * 256;      // 2048 float4 each
        int row = idx >> 4;
        int c4 = idx & 15;
        CP16(smem_u32(Qs + row * PITCH + c4 * 4),
             Q + (size_t)(r0 + row) * Dv + c4 * 4);
        CP16(smem_u32(Ks + row * PITCH + c4 * 4),
             Kp + (size_t)(c0 + row) * Dv + c4 * 4);
    }
    CP_COMMIT();
    CP_WAIT0();
    __syncthreads();

    int lane = tid & 31, wid = tid >> 5;
    int wm = wid >> 2, wn = wid & 3;
    int lr = lane >> 2, lc = lane & 3;

    float4 acc[4][4];
#pragma unroll
    for (int i = 0; i < 4; i++)
#pragma unroll
        for (int j = 0; j < 4; j++) acc[i][j] = make_float4(0.f, 0.f, 0.f, 0.f);

#pragma unroll
    for (int kk = 0; kk < 64; kk += 8) {
        uint32_t af[4][4];
#pragma unroll
        for (int mt = 0; mt < 4; mt++) {
            int row = wm * 64 + mt * 16 + lr;
            af[mt][0] = __float_as_uint(Qs[row * PITCH + kk + lc]);
            af[mt][1] = __float_as_uint(Qs[(row + 8) * PITCH + kk + lc]);
            af[mt][2] = __float_as_uint(Qs[row * PITCH + kk + lc + 4]);
            af[mt][3] = __float_as_uint(Qs[(row + 8) * PITCH + kk + lc + 4]);
        }
        uint32_t bf[4][2];
#pragma unroll
        for (int nt = 0; nt < 4; nt++) {
            int n = wn * 32 + nt * 8 + lr;
            bf[nt][0] = __float_as_uint(Ks[n * PITCH + kk + lc]);
            bf[nt][1] = __float_as_uint(Ks[n * PITCH + kk + lc + 4]);
        }
#pragma unroll
        for (int mt = 0; mt < 4; mt++)
#pragma unroll
            for (int nt = 0; nt < 4; nt++)
                MMA_TF32(acc[mt][nt], af[mt], bf[nt]);
    }

    const float scale = 0.125f;
#pragma unroll
    for (int mt = 0; mt < 4; mt++) {
#pragma unroll
        for (int nt = 0; nt < 4; nt++) {
            int col = c0 + wn * 32 + nt * 8 + lc * 2;
#pragma unroll
            for (int half = 0; half < 2; half++) {
                int r = r0 + wm * 64 + mt * 16 + lr + half * 8;
                float v0 = (half ? acc[mt][nt].z : acc[mt][nt].x) * scale;
                float v1 = (half ? acc[mt][nt].w : acc[mt][nt].y) * scale;
                if (col > r) v0 = 0.f;
                if (col + 1 > r) v1 = 0.f;
                *(float2*)(out + (size_t)r * Sv + col) = make_float2(v0, v1);
            }
        }
    }
}

// ============================================================
// Kernel 3 (R1, measured): in-place row softmax, one warp/row.
// ============================================================
__global__ void __launch_bounds__(256) softmax_kernel(float* __restrict__ W) {
    int gwarp = (blockIdx.x * 256 + threadIdx.x) >> 5;
    int lane = threadIdx.x & 31;
    int bh = gwarp >> 11;
    int q = gwarp & 2047;
    float* row = W + ((size_t)bh * Sv + q) * Sv;
    int L = q + 1;

    float4 v[16];
    float mx = -1e30f;
#pragma unroll
    for (int it = 0; it < 16; it++) {
        int j = (it * 32 + lane) * 4;
        if (j < L) {
            v[it] = *(const float4*)(row + j);
            mx = fmaxf(mx, v[it].x);
            if (j + 1 < L) mx = fmaxf(mx, v[it].y);
            if (j + 2 < L) mx = fmaxf(mx, v[it].z);
            if (j + 3 < L) mx = fmaxf(mx, v[it].w);
        } else {
            v[it] = make_float4(0.f, 0.f, 0.f, 0.f);
        }
    }
#pragma unroll
    for (int o = 16; o; o >>= 1) mx = fmaxf(mx, __shfl_xor_sync(0xffffffffu, mx, o));

    float sum = 0.f;
#pragma unroll
    for (int it = 0; it < 16; it++) {
        int j = (it * 32 + lane) * 4;
        float e0 = (j + 0 < L) ? __expf(v[it].x - mx) : 0.f;
        float e1 = (j + 1 < L) ? __expf(v[it].y - mx) : 0.f;
        float e2 = (j + 2 < L) ? __expf(v[it].z - mx) : 0.f;
        float e3 = (j + 3 < L) ? __expf(v[it].w - mx) : 0.f;
        v[it] = make_float4(e0, e1, e2, e3);
        sum += e0 + e1 + e2 + e3;
    }
#pragma unroll
    for (int o = 16; o; o >>= 1) sum += __shfl_xor_sync(0xffffffffu, sum, o);
    float inv = 1.0f / sum;

#pragma unroll
    for (int it = 0; it < 16; it++) {
        int j = (it * 32 + lane) * 4;
        if (j + 3 < L) {
            *(float4*)(row + j) = make_float4(v[it].x * inv, v[it].y * inv,
                                              v[it].z * inv, v[it].w * inv);
        } else if (j < L) {
            row[j] = v[it].x * inv;
            if (j + 1 < L) row[j + 1] = v[it].y * inv;
            if (j + 2 < L) row[j + 2] = v[it].z * inv;
        }
    }
}

// ============================================================
// Kernel 4: PV (mma tf32). P read (cvt in-loop), V pre-rounded.
// Block: 128q x 64d, 8 warps (4x2), warp tile 32x32. BK=32,
// cp.async double-buffered. Dynamic smem 55296 B:
//   Ps[2][128][36] at 0, Vs[2][32][72] at 9216 floats.
// ============================================================
__global__ void __launch_bounds__(256) pv_mma(const float* __restrict__ Wts) {
    int bh = blockIdx.y;
    int rt = (gridDim.x - 1) - blockIdx.x;   // heavy row-tiles first
    int r0 = rt * 128;
    const float* P = Wts + (size_t)bh * Sv * Sv;
    const float* V = g_V + (size_t)bh * Sv * Dv;

    extern __shared__ float sm[];
    const int PP = 36, VP = 72;
    const int PBUF = 128 * PP;     // 4608
    const int VBUF = 32 * VP;      // 2304
    float* Ps = sm;
    float* Vs = sm + 2 * PBUF;

    int tid = threadIdx.x, lane = tid & 31, wid = tid >> 5;
    int wm = wid >> 1, wn = wid & 1;
    int lr = lane >> 2, lc = lane & 3;

    float4 acc[2][4];
#pragma unroll
    for (int i = 0; i < 2; i++)
#pragma unroll
        for (int j = 0; j < 4; j++) acc[i][j] = make_float4(0.f, 0.f, 0.f, 0.f);

    int kend = r0 + 128;
    int nit = kend >> 5;

    // prologue
    {
#pragma unroll
        for (int it = 0; it < 4; it++) {
            int idx = tid + it * 256;
            int row = idx >> 3, c4 = idx & 7;
            CP16(smem_u32(Ps + row * PP + c4 * 4),
                 P + (size_t)(r0 + row) * Sv + c4 * 4);
        }
#pragma unroll
        for (int it = 0; it < 2; it++) {
            int idx = tid + it * 256;
            int row = idx >> 4, c4 = idx & 15;
            CP16(smem_u32(Vs + row * VP + c4 * 4),
                 V + (size_t)row * Dv + c4 * 4);
        }
        CP_COMMIT();
    }

    for (int itk = 0; itk < nit; itk++) {
        int buf = itk & 1;
        if (itk + 1 < nit) {
            int kc = (itk + 1) * 32;
            int nb = buf ^ 1;
#pragma unroll
            for (int it = 0; it < 4; it++) {
                int idx = tid + it * 256;
                int row = idx >> 3, c4 = idx & 7;
                CP16(smem_u32(Ps + nb * PBUF + row * PP + c4 * 4),
                     P + (size_t)(r0 + row) * Sv + kc + c4 * 4);
            }
#pragma unroll
            for (int it = 0; it < 2; it++) {
                int idx = tid + it * 256;
                int row = idx >> 4, c4 = idx & 15;
                CP16(smem_u32(Vs + nb * VBUF + row * VP + c4 * 4),
                     V + (size_t)(kc + row) * Dv + c4 * 4);
            }
            CP_COMMIT();
            CP_WAIT1();
        } else {
            CP_WAIT0();
        }
        __syncthreads();

        const float* Pb = Ps + buf * PBUF;
        const float* Vb = Vs + buf * VBUF;
#pragma unroll
        for (int kk = 0; kk < 32; kk += 8) {
            uint32_t af[2][4];
#pragma unroll
            for (int mt = 0; mt < 2; mt++) {
                int row = wm * 32 + mt * 16 + lr;
                af[mt][0] = cvt_tf32(Pb[row * PP + kk + lc]);
                af[mt][1] = cvt_tf32(Pb[(row + 8) * PP + kk + lc]);
                af[mt][2] = cvt_tf32(Pb[row * PP + kk + lc + 4]);
                af[mt][3] = cvt_tf32(Pb[(row + 8) * PP + kk + lc + 4]);
            }
            uint32_t bf[4][2];
#pragma unroll
            for (int nt = 0; nt < 4; nt++) {
                int n = wn * 32 + nt * 8 + lr;
                bf[nt][0] = __float_as_uint(Vb[(kk + lc) * VP + n]);
                bf[nt][1] = __float_as_uint(Vb[(kk + 4 + lc) * VP + n]);
            }
#pragma unroll
            for (int mt = 0; mt < 2; mt++)
#pragma unroll
                for (int nt = 0; nt < 4; nt++)
                    MMA_TF32(acc[mt][nt], af[mt], bf[nt]);
        }
        __syncthreads();
    }

    int b = bh >> 4, h = bh & 15;
#pragma unroll
    for (int mt = 0; mt < 2; mt++) {
#pragma unroll
        for (int nt = 0; nt < 4; nt++) {
            int d = wn * 32 + nt * 8 + lc * 2;
#pragma unroll
            for (int half = 0; half < 2; half++) {
                int r = r0 + wm * 32 + mt * 16 + lr + half * 8;
                float v0 = half ? acc[mt][nt].z : acc[mt][nt].x;
                float v1 = half ? acc[mt][nt].w : acc[mt][nt].y;
                float* dp = g_AO + ((size_t)(b * Sv + r)) * Ev + h * Dv + d;
                *(float2*)dp = make_float2(tf32f(v0), tf32f(v1));
            }
        }
    }
}

// ============================================================
// Launch
// ============================================================
extern "C" void kernel_launch(void* const* d_in, const int* in_sizes, int n_in,
                              void* d_out, int out_size) {
    const float* hs     = (const float*)d_in[0];
    const float* w_attn = (const float*)d_in[1];
    const float* b_attn = (const float*)d_in[2];
    const float* w_proj = (const float*)d_in[3];
    const float* b_proj = (const float*)d_in[4];
    float* out = (float*)d_out;

    const size_t AO_N = (size_t)Bv * Sv * Ev;
    const size_t W_N  = (size_t)Bv * Hv * Sv * Sv;

    float* wts;
    if ((size_t)out_size >= AO_N + W_N) {
        wts = out + AO_N;
    } else {
        void* p = nullptr;
        cudaGetSymbolAddress(&p, g_Wscratch);
        wts = (float*)p;
    }

    float* hr;  { void* p = nullptr; cudaGetSymbolAddress(&p, g_HR);  hr  = (float*)p; }
    float* wat; { void* p = nullptr; cudaGetSymbolAddress(&p, g_WAT); wat = (float*)p; }
    float* wpt; { void* p = nullptr; cudaGetSymbolAddress(&p, g_WPT); wpt = (float*)p; }

    const int GEMM_SMEM = 40960;
    const int SCORES_SMEM = 2 * 128 * 68 * 4;   // 69632
    const int PV_SMEM = (2 * 128 * 36 + 2 * 32 * 72) * 4;  // 55296
    cudaFuncSetAttribute(qkv_gemm_mma,
                         cudaFuncAttributeMaxDynamicSharedMemorySize, GEMM_SMEM);
    cudaFuncSetAttribute(proj_gemm_mma,
                         cudaFuncAttributeMaxDynamicSharedMemorySize, GEMM_SMEM);
    cudaFuncSetAttribute(scores_mma,
                         cudaFuncAttributeMaxDynamicSharedMemorySize, SCORES_SMEM);
    cudaFuncSetAttribute(pv_mma,
                         cudaFuncAttributeMaxDynamicSharedMemorySize, PV_SMEM);

    // pre-passes: tf32-round hidden; transpose+round weights
    round_tf32_kernel<<<(Bv * Sv * Ev) / (256 * 4), 256>>>(hs, hr);
    transpose_k<<<dim3(N3 / 32, Ev / 32), dim3(32, 8)>>>(w_attn, wat, Ev, N3);
    transpose_k<<<dim3(Ev / 32, Ev / 32), dim3(32, 8)>>>(w_proj, wpt, Ev, Ev);

    qkv_gemm_mma<<<dim3(N3 / 128, (Bv * Sv) / 128), 256, GEMM_SMEM>>>(b_attn);
    scores_mma<<<dim3(Sv / 128, Sv / 128, BHv), 256, SCORES_SMEM>>>(wts);
    softmax_kernel<<<(BHv * Sv) / 8, 256>>>(wts);
    pv_mma<<<dim3(Sv / 128, BHv), 256, PV_SMEM>>>(wts);
    proj_gemm_mma<<<dim3(Ev / 128, (Bv * Sv) / 128), 256, GEMM_SMEM>>>(b_proj, out);
}